// round 1
// baseline (speedup 1.0000x reference)
#include <cuda_runtime.h>
#include <cstdint>

// ---------------------------------------------------------------------------
// Problem constants
// ---------------------------------------------------------------------------
#define BB    4
#define SEQ   2048
#define EMB   1024
#define NH    16
#define HD    64
#define MTOT  (BB * SEQ)          // 8192 rows
#define NQKV  (3 * EMB)           // 3072
#define ATT_SCALE 0.125f          // 64^-0.5

// ---------------------------------------------------------------------------
// Scratch (device globals: allocation-free)
// ---------------------------------------------------------------------------
__device__ float g_q[(size_t)BB * NH * SEQ * HD];   // [b,h,n,d]
__device__ float g_k[(size_t)BB * NH * SEQ * HD];
__device__ float g_v[(size_t)BB * NH * SEQ * HD];
__device__ float g_att[(size_t)MTOT * EMB];         // [b,n,h*d]

// ---------------------------------------------------------------------------
// Helpers
// ---------------------------------------------------------------------------
__device__ __forceinline__ float to_tf32(float x) {
    uint32_t u;
    asm("cvt.rna.tf32.f32 %0, %1;" : "=r"(u) : "f"(x));
    return __uint_as_float(u);
}

__device__ __forceinline__ void mma8(float& c0, float& c1, float& c2, float& c3,
                                     uint32_t a0, uint32_t a1, uint32_t a2, uint32_t a3,
                                     uint32_t b0, uint32_t b1) {
    asm volatile(
        "mma.sync.aligned.m16n8k8.row.col.f32.tf32.tf32.f32 "
        "{%0,%1,%2,%3}, {%4,%5,%6,%7}, {%8,%9}, {%0,%1,%2,%3};"
        : "+f"(c0), "+f"(c1), "+f"(c2), "+f"(c3)
        : "r"(a0), "r"(a1), "r"(a2), "r"(a3), "r"(b0), "r"(b1));
}

__device__ __forceinline__ uint32_t fb(float x) { return __float_as_uint(x); }

// QKV scatter: global C col c in [0,3072) -> which (q/k/v), head, dim
__device__ __forceinline__ void qkv_store(int m, int c, float val) {
    int which = c >> 10;
    int r = c & 1023;
    int h = r >> 6;
    int d = r & 63;
    int b = m >> 11;
    int n = m & 2047;
    size_t off = (((size_t)(b * NH + h)) * SEQ + n) * HD + d;
    float* dst = (which == 0) ? g_q : (which == 1) ? g_k : g_v;
    dst[off] = val;
}

// ---------------------------------------------------------------------------
// Generic tf32 GEMM: C[M x N] = A[M x K] * B[K x N]  (row-major A and B)
// MODE 0: C = ... + bias (write to C)
// MODE 1: scatter into g_q/g_k/g_v
// Tile: 128x128x32, 256 threads, warps 2(m) x 4(n), warp tile 64x32.
// ---------------------------------------------------------------------------
template <int MODE>
__global__ __launch_bounds__(256)
void gemm_tf32(const float* __restrict__ A, const float* __restrict__ Bm,
               const float* __restrict__ bias, float* __restrict__ C,
               int N, int K) {
    __shared__ float As[128][36];   // [row][k], pad->stride 36: conflict-free frag loads
    __shared__ float Bs[32][136];   // [k][col], pad->stride 136: conflict-free frag loads

    const int t = threadIdx.x;
    const int lane = t & 31;
    const int warp = t >> 5;
    const int wm = warp >> 2;       // 0..1
    const int wn = warp & 3;        // 0..3
    const int lr = lane >> 2;       // 0..7
    const int lc = lane & 3;        // 0..3
    const int m0 = blockIdx.y * 128;
    const int n0 = blockIdx.x * 128;

    float acc[4][4][4];
#pragma unroll
    for (int mt = 0; mt < 4; mt++)
#pragma unroll
        for (int nt = 0; nt < 4; nt++)
#pragma unroll
            for (int e = 0; e < 4; e++) acc[mt][nt][e] = 0.f;

    for (int kc = 0; kc < K; kc += 32) {
        // --- load A tile (128x32) and B tile (32x128) ---
#pragma unroll
        for (int j = 0; j < 4; j++) {
            int idx = t + j * 256;              // 0..1023
            int ra = idx >> 3;                  // 0..127
            int ca = (idx & 7) << 2;            // 0,4,..,28
            float4 va = *(const float4*)(A + (size_t)(m0 + ra) * K + kc + ca);
            As[ra][ca + 0] = to_tf32(va.x);
            As[ra][ca + 1] = to_tf32(va.y);
            As[ra][ca + 2] = to_tf32(va.z);
            As[ra][ca + 3] = to_tf32(va.w);

            int rb = idx >> 5;                  // 0..31
            int cb = (idx & 31) << 2;           // 0..124
            float4 vb = *(const float4*)(Bm + (size_t)(kc + rb) * N + n0 + cb);
            Bs[rb][cb + 0] = to_tf32(vb.x);
            Bs[rb][cb + 1] = to_tf32(vb.y);
            Bs[rb][cb + 2] = to_tf32(vb.z);
            Bs[rb][cb + 3] = to_tf32(vb.w);
        }
        __syncthreads();

#pragma unroll
        for (int ks = 0; ks < 4; ks++) {
            uint32_t af[4][4];
#pragma unroll
            for (int mt = 0; mt < 4; mt++) {
                int rbse = wm * 64 + mt * 16;
                af[mt][0] = fb(As[rbse + lr][ks * 8 + lc]);
                af[mt][1] = fb(As[rbse + lr + 8][ks * 8 + lc]);
                af[mt][2] = fb(As[rbse + lr][ks * 8 + lc + 4]);
                af[mt][3] = fb(As[rbse + lr + 8][ks * 8 + lc + 4]);
            }
            uint32_t bfr[4][2];
#pragma unroll
            for (int nt = 0; nt < 4; nt++) {
                int cb = wn * 32 + nt * 8 + lr;
                bfr[nt][0] = fb(Bs[ks * 8 + lc][cb]);
                bfr[nt][1] = fb(Bs[ks * 8 + lc + 4][cb]);
            }
#pragma unroll
            for (int mt = 0; mt < 4; mt++)
#pragma unroll
                for (int nt = 0; nt < 4; nt++)
                    mma8(acc[mt][nt][0], acc[mt][nt][1], acc[mt][nt][2], acc[mt][nt][3],
                         af[mt][0], af[mt][1], af[mt][2], af[mt][3],
                         bfr[nt][0], bfr[nt][1]);
        }
        __syncthreads();
    }

    // --- epilogue ---
#pragma unroll
    for (int mt = 0; mt < 4; mt++) {
#pragma unroll
        for (int nt = 0; nt < 4; nt++) {
            int r = m0 + wm * 64 + mt * 16 + lr;
            int c = n0 + wn * 32 + nt * 8 + 2 * lc;
            if (MODE == 0) {
                float b0 = bias[c], b1 = bias[c + 1];
                C[(size_t)r * N + c]           = acc[mt][nt][0] + b0;
                C[(size_t)r * N + c + 1]       = acc[mt][nt][1] + b1;
                C[(size_t)(r + 8) * N + c]     = acc[mt][nt][2] + b0;
                C[(size_t)(r + 8) * N + c + 1] = acc[mt][nt][3] + b1;
            } else {
                qkv_store(r, c, acc[mt][nt][0]);
                qkv_store(r, c + 1, acc[mt][nt][1]);
                qkv_store(r + 8, c, acc[mt][nt][2]);
                qkv_store(r + 8, c + 1, acc[mt][nt][3]);
            }
        }
    }
}

// ---------------------------------------------------------------------------
// Flash attention: one CTA per (b*h, 128-row Q tile). 256 threads.
// S-phase warps: 4(m:32) x 2(n:64).  O-phase warps: 4(m:32) x 2(n:32).
// ---------------------------------------------------------------------------
#define SQS 68    // sQ stride (conflict-free A-frag loads)
#define SKS 68    // sK stride
#define SVS 72    // sV stride (conflict-free B-frag loads)
#define SSS 132   // sS stride

#define ATTN_SMEM_FLOATS (128 * (SQS + SKS + SVS + SSS) + 3 * 128)
#define ATTN_SMEM_BYTES  (ATTN_SMEM_FLOATS * 4)

__global__ __launch_bounds__(256)
void attn_kernel() {
    extern __shared__ float sm[];
    float* sQ = sm;
    float* sK = sQ + 128 * SQS;
    float* sV = sK + 128 * SKS;
    float* sS = sV + 128 * SVS;
    float* ms = sS + 128 * SSS;
    float* ls = ms + 128;
    float* cs = ls + 128;

    const int t = threadIdx.x;
    const int lane = t & 31;
    const int warp = t >> 5;
    const int lr = lane >> 2;
    const int lc = lane & 3;
    const int wm = warp >> 1;    // 0..3  (rows, x32)
    const int wn = warp & 1;     // 0..1
    const int bh = blockIdx.y;
    const int q0 = blockIdx.x * 128;
    const size_t base = (size_t)bh * SEQ * HD;

    // load Q tile [128 x 64]
#pragma unroll
    for (int j = 0; j < 8; j++) {
        int idx = t + j * 256;
        int r = idx >> 4;
        int c4 = (idx & 15) << 2;
        float4 v = *(const float4*)(g_q + base + (size_t)(q0 + r) * HD + c4);
        sQ[r * SQS + c4 + 0] = to_tf32(v.x);
        sQ[r * SQS + c4 + 1] = to_tf32(v.y);
        sQ[r * SQS + c4 + 2] = to_tf32(v.z);
        sQ[r * SQS + c4 + 3] = to_tf32(v.w);
    }
    if (t < 128) { ms[t] = -1e30f; ls[t] = 0.f; }

    float accO[2][4][4];
#pragma unroll
    for (int mt = 0; mt < 2; mt++)
#pragma unroll
        for (int nt = 0; nt < 4; nt++)
#pragma unroll
            for (int e = 0; e < 4; e++) accO[mt][nt][e] = 0.f;

    for (int kt = 0; kt < SEQ / 128; kt++) {
        __syncthreads();   // previous P.V / softmax done with sK, sV, sS
        const int k0 = kt * 128;
#pragma unroll
        for (int j = 0; j < 8; j++) {
            int idx = t + j * 256;
            int r = idx >> 4;
            int c4 = (idx & 15) << 2;
            float4 kv = *(const float4*)(g_k + base + (size_t)(k0 + r) * HD + c4);
            sK[r * SKS + c4 + 0] = to_tf32(kv.x);
            sK[r * SKS + c4 + 1] = to_tf32(kv.y);
            sK[r * SKS + c4 + 2] = to_tf32(kv.z);
            sK[r * SKS + c4 + 3] = to_tf32(kv.w);
            float4 vv = *(const float4*)(g_v + base + (size_t)(k0 + r) * HD + c4);
            sV[r * SVS + c4 + 0] = to_tf32(vv.x);
            sV[r * SVS + c4 + 1] = to_tf32(vv.y);
            sV[r * SVS + c4 + 2] = to_tf32(vv.z);
            sV[r * SVS + c4 + 3] = to_tf32(vv.w);
        }
        __syncthreads();

        // ---- S = Q * K^T : warp tile 32(m) x 64(n) ----
        float accS[2][8][4];
#pragma unroll
        for (int mt = 0; mt < 2; mt++)
#pragma unroll
            for (int nt = 0; nt < 8; nt++)
#pragma unroll
                for (int e = 0; e < 4; e++) accS[mt][nt][e] = 0.f;

#pragma unroll
        for (int ks = 0; ks < 8; ks++) {
            uint32_t af[2][4];
#pragma unroll
            for (int mt = 0; mt < 2; mt++) {
                int rb = wm * 32 + mt * 16;
                af[mt][0] = fb(sQ[(rb + lr) * SQS + ks * 8 + lc]);
                af[mt][1] = fb(sQ[(rb + lr + 8) * SQS + ks * 8 + lc]);
                af[mt][2] = fb(sQ[(rb + lr) * SQS + ks * 8 + lc + 4]);
                af[mt][3] = fb(sQ[(rb + lr + 8) * SQS + ks * 8 + lc + 4]);
            }
            uint32_t bfr[8][2];
#pragma unroll
            for (int nt = 0; nt < 8; nt++) {
                int n = wn * 64 + nt * 8 + lr;
                bfr[nt][0] = fb(sK[n * SKS + ks * 8 + lc]);
                bfr[nt][1] = fb(sK[n * SKS + ks * 8 + lc + 4]);
            }
#pragma unroll
            for (int mt = 0; mt < 2; mt++)
#pragma unroll
                for (int nt = 0; nt < 8; nt++)
                    mma8(accS[mt][nt][0], accS[mt][nt][1], accS[mt][nt][2], accS[mt][nt][3],
                         af[mt][0], af[mt][1], af[mt][2], af[mt][3],
                         bfr[nt][0], bfr[nt][1]);
        }
#pragma unroll
        for (int mt = 0; mt < 2; mt++)
#pragma unroll
            for (int nt = 0; nt < 8; nt++) {
                int r = wm * 32 + mt * 16 + lr;
                int c = wn * 64 + nt * 8 + 2 * lc;
                sS[r * SSS + c]           = accS[mt][nt][0] * ATT_SCALE;
                sS[r * SSS + c + 1]       = accS[mt][nt][1] * ATT_SCALE;
                sS[(r + 8) * SSS + c]     = accS[mt][nt][2] * ATT_SCALE;
                sS[(r + 8) * SSS + c + 1] = accS[mt][nt][3] * ATT_SCALE;
            }
        __syncthreads();

        // ---- online softmax: one thread per row ----
        if (t < 128) {
            float* Sr = sS + t * SSS;
            float mo = ms[t];
            float mx = mo;
#pragma unroll 4
            for (int j = 0; j < 128; j++) mx = fmaxf(mx, Sr[j]);
            float cr = __expf(mo - mx);
            float sum = 0.f;
#pragma unroll 4
            for (int j = 0; j < 128; j++) {
                float p = __expf(Sr[j] - mx);
                sum += p;
                Sr[j] = to_tf32(p);
            }
            ls[t] = ls[t] * cr + sum;
            ms[t] = mx;
            cs[t] = cr;
        }
        __syncthreads();

        // ---- rescale O, then O += P * V : warp tile 32(m) x 32(n) ----
#pragma unroll
        for (int mt = 0; mt < 2; mt++) {
            float f0 = cs[wm * 32 + mt * 16 + lr];
            float f1 = cs[wm * 32 + mt * 16 + lr + 8];
#pragma unroll
            for (int nt = 0; nt < 4; nt++) {
                accO[mt][nt][0] *= f0;
                accO[mt][nt][1] *= f0;
                accO[mt][nt][2] *= f1;
                accO[mt][nt][3] *= f1;
            }
        }
#pragma unroll
        for (int ks = 0; ks < 16; ks++) {
            uint32_t af[2][4];
#pragma unroll
            for (int mt = 0; mt < 2; mt++) {
                int rb = wm * 32 + mt * 16;
                af[mt][0] = fb(sS[(rb + lr) * SSS + ks * 8 + lc]);
                af[mt][1] = fb(sS[(rb + lr + 8) * SSS + ks * 8 + lc]);
                af[mt][2] = fb(sS[(rb + lr) * SSS + ks * 8 + lc + 4]);
                af[mt][3] = fb(sS[(rb + lr + 8) * SSS + ks * 8 + lc + 4]);
            }
            uint32_t bfr[4][2];
#pragma unroll
            for (int nt = 0; nt < 4; nt++) {
                int d = wn * 32 + nt * 8 + lr;
                bfr[nt][0] = fb(sV[(ks * 8 + lc) * SVS + d]);
                bfr[nt][1] = fb(sV[(ks * 8 + lc + 4) * SVS + d]);
            }
#pragma unroll
            for (int mt = 0; mt < 2; mt++)
#pragma unroll
                for (int nt = 0; nt < 4; nt++)
                    mma8(accO[mt][nt][0], accO[mt][nt][1], accO[mt][nt][2], accO[mt][nt][3],
                         af[mt][0], af[mt][1], af[mt][2], af[mt][3],
                         bfr[nt][0], bfr[nt][1]);
        }
    }

    // ---- normalize & store to g_att in [b, n, h*64+d] layout ----
    const int b = bh >> 4;
    const int h = bh & 15;
#pragma unroll
    for (int mt = 0; mt < 2; mt++) {
        int r = wm * 32 + mt * 16 + lr;
        float i0 = 1.f / ls[r];
        float i1 = 1.f / ls[r + 8];
        int q = q0 + r;
#pragma unroll
        for (int nt = 0; nt < 4; nt++) {
            int d = wn * 32 + nt * 8 + 2 * lc;
            size_t o0 = ((size_t)(b * SEQ + q)) * EMB + h * HD + d;
            size_t o1 = ((size_t)(b * SEQ + q + 8)) * EMB + h * HD + d;
            g_att[o0]     = accO[mt][nt][0] * i0;
            g_att[o0 + 1] = accO[mt][nt][1] * i0;
            g_att[o1]     = accO[mt][nt][2] * i1;
            g_att[o1 + 1] = accO[mt][nt][3] * i1;
        }
    }
}

// ---------------------------------------------------------------------------
// Launch
// ---------------------------------------------------------------------------
extern "C" void kernel_launch(void* const* d_in, const int* in_sizes, int n_in,
                              void* d_out, int out_size) {
    const float* x    = (const float*)d_in[0];
    const float* Wqkv = (const float*)d_in[1];
    const float* Wout = (const float*)d_in[2];
    const float* bout = (const float*)d_in[3];
    float* out = (float*)d_out;

    // 1) QKV projection with head-split scatter epilogue
    gemm_tf32<1><<<dim3(NQKV / 128, MTOT / 128), 256>>>(x, Wqkv, nullptr, nullptr,
                                                        NQKV, EMB);

    // 2) flash attention
    cudaFuncSetAttribute(attn_kernel, cudaFuncAttributeMaxDynamicSharedMemorySize,
                         ATTN_SMEM_BYTES);
    attn_kernel<<<dim3(SEQ / 128, BB * NH), 256, ATTN_SMEM_BYTES>>>();

    // 3) output projection + bias
    void* attp = nullptr;
    cudaGetSymbolAddress(&attp, g_att);
    gemm_tf32<0><<<dim3(EMB / 128, MTOT / 128), 256>>>((const float*)attp, Wout,
                                                       bout, out, EMB, EMB);
}

// round 2
// speedup vs baseline: 2.0289x; 2.0289x over previous
#include <cuda_runtime.h>
#include <cstdint>

// ---------------------------------------------------------------------------
// Problem constants
// ---------------------------------------------------------------------------
#define BB    4
#define SEQ   2048
#define EMB   1024
#define NH    16
#define HD    64
#define MTOT  (BB * SEQ)          // 8192 rows
#define NQKV  (3 * EMB)           // 3072

// ---------------------------------------------------------------------------
// Scratch (device globals: allocation-free)
// ---------------------------------------------------------------------------
__device__ float g_q[(size_t)BB * NH * SEQ * HD];   // [b,h,n,d] tf32, pre-scaled
__device__ float g_k[(size_t)BB * NH * SEQ * HD];   // tf32
__device__ float g_v[(size_t)BB * NH * SEQ * HD];   // tf32
__device__ float g_att[(size_t)MTOT * EMB];         // [b,n,h*d] fp32

// ---------------------------------------------------------------------------
// Helpers
// ---------------------------------------------------------------------------
__device__ __forceinline__ float to_tf32(float x) {
    uint32_t u;
    asm("cvt.rna.tf32.f32 %0, %1;" : "=r"(u) : "f"(x));
    return __uint_as_float(u);
}
__device__ __forceinline__ uint32_t fb(float x) { return __float_as_uint(x); }
__device__ __forceinline__ uint32_t fbt(float x) { return fb(to_tf32(x)); }

__device__ __forceinline__ void mma8(float& c0, float& c1, float& c2, float& c3,
                                     uint32_t a0, uint32_t a1, uint32_t a2, uint32_t a3,
                                     uint32_t b0, uint32_t b1) {
    asm volatile(
        "mma.sync.aligned.m16n8k8.row.col.f32.tf32.tf32.f32 "
        "{%0,%1,%2,%3}, {%4,%5,%6,%7}, {%8,%9}, {%0,%1,%2,%3};"
        : "+f"(c0), "+f"(c1), "+f"(c2), "+f"(c3)
        : "r"(a0), "r"(a1), "r"(a2), "r"(a3), "r"(b0), "r"(b1));
}

__device__ __forceinline__ void cpa16(float* dst, const float* src) {
    uint32_t d = (uint32_t)__cvta_generic_to_shared(dst);
    asm volatile("cp.async.cg.shared.global [%0], [%1], 16;" :: "r"(d), "l"(src));
}
__device__ __forceinline__ void cpa_commit() {
    asm volatile("cp.async.commit_group;");
}
template <int N>
__device__ __forceinline__ void cpa_wait() {
    asm volatile("cp.async.wait_group %0;" :: "n"(N));
}

// QKV scatter: store tf32; fold softmax scale (2^-3, exact) into Q
__device__ __forceinline__ void qkv_store(int m, int c, float val) {
    int which = c >> 10;
    int r = c & 1023;
    int h = r >> 6;
    int d = r & 63;
    int b = m >> 11;
    int n = m & 2047;
    size_t off = (((size_t)(b * NH + h)) * SEQ + n) * HD + d;
    if (which == 0)      g_q[off] = to_tf32(val * 0.125f);
    else if (which == 1) g_k[off] = to_tf32(val);
    else                 g_v[off] = to_tf32(val);
}

// ---------------------------------------------------------------------------
// tf32 GEMM, 2-stage cp.async pipeline.
// C[MxN] = A[MxK]*B[KxN], row-major. 128x128x32 tile, 256 thr, warps 2x4.
// MODE 0: C = acc + bias ; MODE 1: scatter into g_q/g_k/g_v
// ---------------------------------------------------------------------------
#define GAS 36      // As row stride
#define GBS 132     // Bs row stride
#define GEMM_SMEM_BYTES ((2 * 128 * GAS + 2 * 32 * GBS) * 4)

template <int MODE>
__global__ __launch_bounds__(256)
void gemm_tf32(const float* __restrict__ A, const float* __restrict__ Bm,
               const float* __restrict__ bias, float* __restrict__ C,
               int N, int K) {
    extern __shared__ float smg[];
    float* As = smg;                      // [2][128*GAS]
    float* Bs = smg + 2 * 128 * GAS;      // [2][32*GBS]

    const int t = threadIdx.x;
    const int lane = t & 31;
    const int warp = t >> 5;
    const int wm = warp >> 2;       // 0..1
    const int wn = warp & 3;        // 0..3
    const int lr = lane >> 2;       // 0..7
    const int lc = lane & 3;        // 0..3
    const int m0 = blockIdx.y * 128;
    const int n0 = blockIdx.x * 128;

    float acc[4][4][4];
#pragma unroll
    for (int mt = 0; mt < 4; mt++)
#pragma unroll
        for (int nt = 0; nt < 4; nt++)
#pragma unroll
            for (int e = 0; e < 4; e++) acc[mt][nt][e] = 0.f;

    auto loadtile = [&](int s, int kc) {
        float* as = As + s * 128 * GAS;
        float* bs = Bs + s * 32 * GBS;
#pragma unroll
        for (int j = 0; j < 4; j++) {
            int idx = t + j * 256;
            int ra = idx >> 3, ca = (idx & 7) << 2;
            cpa16(as + ra * GAS + ca, A + (size_t)(m0 + ra) * K + kc + ca);
            int rb = idx >> 5, cb = (idx & 31) << 2;
            cpa16(bs + rb * GBS + cb, Bm + (size_t)(kc + rb) * N + n0 + cb);
        }
    };

    const int nk = K >> 5;
    loadtile(0, 0);
    cpa_commit();

    for (int kci = 0; kci < nk; kci++) {
        const int s = kci & 1;
        if (kci + 1 < nk) {
            loadtile(s ^ 1, (kci + 1) << 5);
            cpa_commit();
            cpa_wait<1>();
        } else {
            cpa_wait<0>();
        }
        __syncthreads();

        const float* as = As + s * 128 * GAS;
        const float* bs = Bs + s * 32 * GBS;
#pragma unroll
        for (int ks = 0; ks < 4; ks++) {
            uint32_t af[4][4];
#pragma unroll
            for (int mt = 0; mt < 4; mt++) {
                int rbse = wm * 64 + mt * 16;
                af[mt][0] = fbt(as[(rbse + lr) * GAS + ks * 8 + lc]);
                af[mt][1] = fbt(as[(rbse + lr + 8) * GAS + ks * 8 + lc]);
                af[mt][2] = fbt(as[(rbse + lr) * GAS + ks * 8 + lc + 4]);
                af[mt][3] = fbt(as[(rbse + lr + 8) * GAS + ks * 8 + lc + 4]);
            }
            uint32_t bfr[4][2];
#pragma unroll
            for (int nt = 0; nt < 4; nt++) {
                int cb = wn * 32 + nt * 8 + lr;
                bfr[nt][0] = fbt(bs[(ks * 8 + lc) * GBS + cb]);
                bfr[nt][1] = fbt(bs[(ks * 8 + lc + 4) * GBS + cb]);
            }
#pragma unroll
            for (int mt = 0; mt < 4; mt++)
#pragma unroll
                for (int nt = 0; nt < 4; nt++)
                    mma8(acc[mt][nt][0], acc[mt][nt][1], acc[mt][nt][2], acc[mt][nt][3],
                         af[mt][0], af[mt][1], af[mt][2], af[mt][3],
                         bfr[nt][0], bfr[nt][1]);
        }
        __syncthreads();
    }

    // --- epilogue ---
#pragma unroll
    for (int mt = 0; mt < 4; mt++) {
#pragma unroll
        for (int nt = 0; nt < 4; nt++) {
            int r = m0 + wm * 64 + mt * 16 + lr;
            int c = n0 + wn * 32 + nt * 8 + 2 * lc;
            if (MODE == 0) {
                float b0 = bias[c], b1 = bias[c + 1];
                C[(size_t)r * N + c]           = acc[mt][nt][0] + b0;
                C[(size_t)r * N + c + 1]       = acc[mt][nt][1] + b1;
                C[(size_t)(r + 8) * N + c]     = acc[mt][nt][2] + b0;
                C[(size_t)(r + 8) * N + c + 1] = acc[mt][nt][3] + b1;
            } else {
                qkv_store(r, c, acc[mt][nt][0]);
                qkv_store(r, c + 1, acc[mt][nt][1]);
                qkv_store(r + 8, c, acc[mt][nt][2]);
                qkv_store(r + 8, c + 1, acc[mt][nt][3]);
            }
        }
    }
}

// ---------------------------------------------------------------------------
// Flash attention v2: CTA = (b*h, 128-row Q tile), 256 threads.
// Each warp owns 16 full rows -> warp-local softmax via shfl.
// K/V double-buffered with cp.async. sS aliases sQ.
// ---------------------------------------------------------------------------
#define SKS 68
#define SVS 72
#define SSS 132
#define ATTN_SMEM_BYTES ((2 * 128 * SKS + 2 * 128 * SVS + 128 * SSS) * 4)

__global__ __launch_bounds__(256)
void attn_kernel() {
    extern __shared__ float sm[];
    float* sKb = sm;                              // [2][128*SKS]
    float* sVb = sm + 2 * 128 * SKS;              // [2][128*SVS]
    float* sQ  = sm + 2 * 128 * SKS + 2 * 128 * SVS;   // [128*SKS], aliased:
    float* sS  = sQ;                              // [128*SSS]

    const int t = threadIdx.x;
    const int lane = t & 31;
    const int warp = t >> 5;       // 0..7
    const int lr = lane >> 2;      // 0..7
    const int lc = lane & 3;       // 0..3
    const int rb = warp * 16;      // warp's row base in tile
    const int bh = blockIdx.y;
    const int q0 = blockIdx.x * 128;
    const size_t base = (size_t)bh * SEQ * HD;

    auto kvload = [&](int s, int kt) {
        float* dk = sKb + s * 128 * SKS;
        float* dv = sVb + s * 128 * SVS;
        const size_t gb = base + (size_t)kt * 128 * HD;
#pragma unroll
        for (int j = 0; j < 8; j++) {
            int i = t + j * 256;
            int r = i >> 4, c4 = (i & 15) << 2;
            cpa16(dk + r * SKS + c4, g_k + gb + r * HD + c4);
            cpa16(dv + r * SVS + c4, g_v + gb + r * HD + c4);
        }
    };

    // Q tile -> smem -> registers (tf32, pre-scaled already)
#pragma unroll
    for (int j = 0; j < 8; j++) {
        int i = t + j * 256;
        int r = i >> 4, c4 = (i & 15) << 2;
        cpa16(sQ + r * SKS + c4, g_q + base + (size_t)(q0 + r) * HD + c4);
    }
    cpa_commit();
    kvload(0, 0);
    cpa_commit();
    cpa_wait<1>();          // Q ready
    __syncthreads();

    uint32_t qf[8][4];
#pragma unroll
    for (int ks = 0; ks < 8; ks++) {
        qf[ks][0] = fb(sQ[(rb + lr) * SKS + ks * 8 + lc]);
        qf[ks][1] = fb(sQ[(rb + lr + 8) * SKS + ks * 8 + lc]);
        qf[ks][2] = fb(sQ[(rb + lr) * SKS + ks * 8 + lc + 4]);
        qf[ks][3] = fb(sQ[(rb + lr + 8) * SKS + ks * 8 + lc + 4]);
    }
    __syncthreads();        // sQ region now reusable as sS

    float m0 = -1e30f, m1 = -1e30f, l0 = 0.f, l1 = 0.f;
    float accO[8][4];
#pragma unroll
    for (int nt = 0; nt < 8; nt++)
#pragma unroll
        for (int e = 0; e < 4; e++) accO[nt][e] = 0.f;

    for (int kt = 0; kt < SEQ / 128; kt++) {
        const int s = kt & 1;
        if (kt + 1 < SEQ / 128) {
            kvload(s ^ 1, kt + 1);
            cpa_commit();
            cpa_wait<1>();
        } else {
            cpa_wait<0>();
        }
        __syncthreads();

        const float* sKs = sKb + s * 128 * SKS;
        const float* sVs = sVb + s * 128 * SVS;

        // ---- S = Q * K^T, warp tile 16 x 128 ----
        float accS[16][4];
#pragma unroll
        for (int nt = 0; nt < 16; nt++)
#pragma unroll
            for (int e = 0; e < 4; e++) accS[nt][e] = 0.f;

#pragma unroll
        for (int nt = 0; nt < 16; nt++) {
#pragma unroll
            for (int ks = 0; ks < 8; ks++) {
                uint32_t b0 = fb(sKs[(nt * 8 + lr) * SKS + ks * 8 + lc]);
                uint32_t b1 = fb(sKs[(nt * 8 + lr) * SKS + ks * 8 + lc + 4]);
                mma8(accS[nt][0], accS[nt][1], accS[nt][2], accS[nt][3],
                     qf[ks][0], qf[ks][1], qf[ks][2], qf[ks][3], b0, b1);
            }
        }

        // ---- warp-local online softmax (rows rb+lr and rb+lr+8) ----
        float mx0 = -1e30f, mx1 = -1e30f;
#pragma unroll
        for (int nt = 0; nt < 16; nt++) {
            mx0 = fmaxf(mx0, fmaxf(accS[nt][0], accS[nt][1]));
            mx1 = fmaxf(mx1, fmaxf(accS[nt][2], accS[nt][3]));
        }
        mx0 = fmaxf(mx0, __shfl_xor_sync(0xffffffffu, mx0, 1));
        mx0 = fmaxf(mx0, __shfl_xor_sync(0xffffffffu, mx0, 2));
        mx1 = fmaxf(mx1, __shfl_xor_sync(0xffffffffu, mx1, 1));
        mx1 = fmaxf(mx1, __shfl_xor_sync(0xffffffffu, mx1, 2));

        float nm0 = fmaxf(m0, mx0), nm1 = fmaxf(m1, mx1);
        float cr0 = __expf(m0 - nm0), cr1 = __expf(m1 - nm1);
        float s0 = 0.f, s1 = 0.f;
#pragma unroll
        for (int nt = 0; nt < 16; nt++) {
            float p0 = __expf(accS[nt][0] - nm0);
            float p1 = __expf(accS[nt][1] - nm0);
            float p2 = __expf(accS[nt][2] - nm1);
            float p3 = __expf(accS[nt][3] - nm1);
            s0 += p0 + p1;
            s1 += p2 + p3;
            float2* lo = (float2*)&sS[(rb + lr) * SSS + nt * 8 + 2 * lc];
            *lo = make_float2(to_tf32(p0), to_tf32(p1));
            float2* hi = (float2*)&sS[(rb + lr + 8) * SSS + nt * 8 + 2 * lc];
            *hi = make_float2(to_tf32(p2), to_tf32(p3));
        }
        s0 += __shfl_xor_sync(0xffffffffu, s0, 1);
        s0 += __shfl_xor_sync(0xffffffffu, s0, 2);
        s1 += __shfl_xor_sync(0xffffffffu, s1, 1);
        s1 += __shfl_xor_sync(0xffffffffu, s1, 2);
        l0 = l0 * cr0 + s0;
        l1 = l1 * cr1 + s1;
        m0 = nm0;
        m1 = nm1;

#pragma unroll
        for (int nt = 0; nt < 8; nt++) {
            accO[nt][0] *= cr0;
            accO[nt][1] *= cr0;
            accO[nt][2] *= cr1;
            accO[nt][3] *= cr1;
        }
        __syncwarp();

        // ---- O += P * V, warp tile 16 x 64 ----
#pragma unroll
        for (int ks = 0; ks < 16; ks++) {
            uint32_t a0 = fb(sS[(rb + lr) * SSS + ks * 8 + lc]);
            uint32_t a1 = fb(sS[(rb + lr + 8) * SSS + ks * 8 + lc]);
            uint32_t a2 = fb(sS[(rb + lr) * SSS + ks * 8 + lc + 4]);
            uint32_t a3 = fb(sS[(rb + lr + 8) * SSS + ks * 8 + lc + 4]);
#pragma unroll
            for (int nt = 0; nt < 8; nt++) {
                uint32_t b0 = fb(sVs[(ks * 8 + lc) * SVS + nt * 8 + lr]);
                uint32_t b1 = fb(sVs[(ks * 8 + lc + 4) * SVS + nt * 8 + lr]);
                mma8(accO[nt][0], accO[nt][1], accO[nt][2], accO[nt][3],
                     a0, a1, a2, a3, b0, b1);
            }
        }
        __syncthreads();   // all warps done with buffer s before overwrite
    }

    // ---- normalize & store [b, n, h*64+d] ----
    const int b = bh >> 4;
    const int h = bh & 15;
    const float i0 = 1.f / l0, i1 = 1.f / l1;
    const int r0g = q0 + rb + lr;
    const int r1g = r0g + 8;
#pragma unroll
    for (int nt = 0; nt < 8; nt++) {
        int d = nt * 8 + 2 * lc;
        *(float2*)&g_att[((size_t)(b * SEQ + r0g)) * EMB + h * HD + d] =
            make_float2(accO[nt][0] * i0, accO[nt][1] * i0);
        *(float2*)&g_att[((size_t)(b * SEQ + r1g)) * EMB + h * HD + d] =
            make_float2(accO[nt][2] * i1, accO[nt][3] * i1);
    }
}

// ---------------------------------------------------------------------------
// Launch
// ---------------------------------------------------------------------------
extern "C" void kernel_launch(void* const* d_in, const int* in_sizes, int n_in,
                              void* d_out, int out_size) {
    const float* x    = (const float*)d_in[0];
    const float* Wqkv = (const float*)d_in[1];
    const float* Wout = (const float*)d_in[2];
    const float* bout = (const float*)d_in[3];
    float* out = (float*)d_out;

    static bool attr_done = false;
    if (!attr_done) {
        cudaFuncSetAttribute(gemm_tf32<1>, cudaFuncAttributeMaxDynamicSharedMemorySize,
                             GEMM_SMEM_BYTES);
        cudaFuncSetAttribute(gemm_tf32<0>, cudaFuncAttributeMaxDynamicSharedMemorySize,
                             GEMM_SMEM_BYTES);
        cudaFuncSetAttribute(attn_kernel, cudaFuncAttributeMaxDynamicSharedMemorySize,
                             ATTN_SMEM_BYTES);
        attr_done = true;
    }

    // 1) QKV projection with head-split tf32 scatter epilogue
    gemm_tf32<1><<<dim3(NQKV / 128, MTOT / 128), 256, GEMM_SMEM_BYTES>>>(
        x, Wqkv, nullptr, nullptr, NQKV, EMB);

    // 2) flash attention
    attn_kernel<<<dim3(SEQ / 128, BB * NH), 256, ATTN_SMEM_BYTES>>>();

    // 3) output projection + bias
    void* attp = nullptr;
    cudaGetSymbolAddress(&attp, g_att);
    gemm_tf32<0><<<dim3(EMB / 128, MTOT / 128), 256, GEMM_SMEM_BYTES>>>(
        (const float*)attp, Wout, bout, out, EMB, EMB);
}

// round 8
// speedup vs baseline: 2.2626x; 1.1152x over previous
#include <cuda_runtime.h>
#include <cstdint>

// ---------------------------------------------------------------------------
// Problem constants
// ---------------------------------------------------------------------------
#define BB    4
#define SEQ   2048
#define EMB   1024
#define NH    16
#define HD    64
#define MTOT  (BB * SEQ)          // 8192 rows
#define NQKV  (3 * EMB)           // 3072
#define KDIM  1024

// ---------------------------------------------------------------------------
// Scratch (device globals: allocation-free)
// ---------------------------------------------------------------------------
__device__ float g_q[(size_t)BB * NH * SEQ * HD];   // [b,h,n,d] tf32, Q pre-scaled
__device__ float g_k[(size_t)BB * NH * SEQ * HD];   // tf32
__device__ float g_v[(size_t)BB * NH * SEQ * HD];   // tf32
__device__ float g_att[(size_t)MTOT * EMB];         // [b,n,h*d] fp32

// ---------------------------------------------------------------------------
// Helpers
// ---------------------------------------------------------------------------
__device__ __forceinline__ float to_tf32(float x) {
    uint32_t u;
    asm("cvt.rna.tf32.f32 %0, %1;" : "=r"(u) : "f"(x));
    return __uint_as_float(u);
}
__device__ __forceinline__ uint32_t fb(float x) { return __float_as_uint(x); }
__device__ __forceinline__ uint32_t fbt(float x) { return fb(to_tf32(x)); }

__device__ __forceinline__ void mma8(float& c0, float& c1, float& c2, float& c3,
                                     uint32_t a0, uint32_t a1, uint32_t a2, uint32_t a3,
                                     uint32_t b0, uint32_t b1) {
    asm volatile(
        "mma.sync.aligned.m16n8k8.row.col.f32.tf32.tf32.f32 "
        "{%0,%1,%2,%3}, {%4,%5,%6,%7}, {%8,%9}, {%0,%1,%2,%3};"
        : "+f"(c0), "+f"(c1), "+f"(c2), "+f"(c3)
        : "r"(a0), "r"(a1), "r"(a2), "r"(a3), "r"(b0), "r"(b1));
}

__device__ __forceinline__ void cpa16(void* dst, const void* src) {
    uint32_t d = (uint32_t)__cvta_generic_to_shared(dst);
    asm volatile("cp.async.cg.shared.global [%0], [%1], 16;" :: "r"(d), "l"(src));
}
__device__ __forceinline__ void cpa_commit() {
    asm volatile("cp.async.commit_group;");
}
template <int N>
__device__ __forceinline__ void cpa_wait() {
    asm volatile("cp.async.wait_group %0;" :: "n"(N));
}

// QKV scatter (vectorized): store tf32; fold softmax scale (2^-3) into Q
__device__ __forceinline__ void qkv_store2(int m, int c, float v0, float v1) {
    int which = c >> 10;
    int r = c & 1023;
    int h = r >> 6;
    int d = r & 63;
    int b = m >> 11;
    int n = m & 2047;
    size_t off = (((size_t)(b * NH + h)) * SEQ + n) * HD + d;
    if (which == 0)
        *(float2*)&g_q[off] = make_float2(to_tf32(v0 * 0.125f), to_tf32(v1 * 0.125f));
    else if (which == 1)
        *(float2*)&g_k[off] = make_float2(to_tf32(v0), to_tf32(v1));
    else
        *(float2*)&g_v[off] = make_float2(to_tf32(v0), to_tf32(v1));
}

// ---------------------------------------------------------------------------
// tf32 GEMM, 3-stage cp.async pipeline. C[M x N] = A[M x 1024] * B[1024 x N].
// CTA tile 128 x (32*WNT), 256 threads, warps 2(m) x 4(n), warp tile 64 x 8*WNT.
// MODE 0: C = acc + bias ; MODE 1: scatter into g_q/g_k/g_v
// WNT = 8 -> CTA-N 256 (GEMM1), WNT = 4 -> CTA-N 128 (GEMM2)
// ---------------------------------------------------------------------------
#define GAS 36
#define GSTAGES 3

template <int MODE, int WNT>
__global__ __launch_bounds__(256, 1)
void gemm_tf32(const float* __restrict__ A, const float* __restrict__ Bm,
               const float* __restrict__ bias, float* __restrict__ C, int N) {
    constexpr int TN  = 32 * WNT;      // CTA N tile
    constexpr int GBS = TN + 8;        // Bs row stride (TN+8 ≡ 8 mod 32: conflict-free)
    constexpr int QPR = TN / 4;        // float4 per B row

    extern __shared__ float smg[];
    float* As = smg;                          // [GSTAGES][128*GAS]
    float* Bs = smg + GSTAGES * 128 * GAS;    // [GSTAGES][32*GBS]

    const int t = threadIdx.x;
    const int lane = t & 31;
    const int warp = t >> 5;
    const int wm = warp >> 2;       // 0..1
    const int wn = warp & 3;        // 0..3
    const int lr = lane >> 2;       // 0..7
    const int lc = lane & 3;        // 0..3
    const int m0 = blockIdx.y * 128;
    const int n0 = blockIdx.x * TN;

    float acc[4][WNT][4];
#pragma unroll
    for (int mt = 0; mt < 4; mt++)
#pragma unroll
        for (int nt = 0; nt < WNT; nt++)
#pragma unroll
            for (int e = 0; e < 4; e++) acc[mt][nt][e] = 0.f;

    auto fill = [&](int s, int kc) {
        float* as = As + s * 128 * GAS;
        float* bs = Bs + s * 32 * GBS;
#pragma unroll
        for (int j = 0; j < 4; j++) {          // A: 128 x 32 floats
            int idx = t + j * 256;
            int ra = idx >> 3, ca = (idx & 7) << 2;
            cpa16(as + ra * GAS + ca, A + (size_t)(m0 + ra) * KDIM + kc + ca);
        }
#pragma unroll
        for (int j = 0; j < WNT; j++) {        // B: 32 x TN floats
            int idx = t + j * 256;
            int rb = idx / QPR, cb = (idx % QPR) << 2;
            cpa16(bs + rb * GBS + cb, Bm + (size_t)(kc + rb) * N + n0 + cb);
        }
    };

    const int NC = KDIM / 32;    // 32 chunks
    fill(0, 0);  cpa_commit();
    fill(1, 32); cpa_commit();

    for (int c = 0; c < NC; c++) {
        if (c + 2 < NC) {
            fill((c + 2) % GSTAGES, (c + 2) * 32);
            cpa_commit();
            cpa_wait<2>();
        } else if (c + 1 < NC) {
            cpa_wait<1>();
        } else {
            cpa_wait<0>();
        }
        __syncthreads();

        const float* as = As + (c % GSTAGES) * 128 * GAS;
        const float* bs = Bs + (c % GSTAGES) * 32 * GBS;
#pragma unroll
        for (int ks = 0; ks < 4; ks++) {
            uint32_t af[4][4];
#pragma unroll
            for (int mt = 0; mt < 4; mt++) {
                int rbse = wm * 64 + mt * 16;
                af[mt][0] = fbt(as[(rbse + lr) * GAS + ks * 8 + lc]);
                af[mt][1] = fbt(as[(rbse + lr + 8) * GAS + ks * 8 + lc]);
                af[mt][2] = fbt(as[(rbse + lr) * GAS + ks * 8 + lc + 4]);
                af[mt][3] = fbt(as[(rbse + lr + 8) * GAS + ks * 8 + lc + 4]);
            }
            uint32_t bfr[WNT][2];
#pragma unroll
            for (int nt = 0; nt < WNT; nt++) {
                int cb = wn * (8 * WNT) + nt * 8 + lr;
                bfr[nt][0] = fbt(bs[(ks * 8 + lc) * GBS + cb]);
                bfr[nt][1] = fbt(bs[(ks * 8 + lc + 4) * GBS + cb]);
            }
#pragma unroll
            for (int mt = 0; mt < 4; mt++)
#pragma unroll
                for (int nt = 0; nt < WNT; nt++)
                    mma8(acc[mt][nt][0], acc[mt][nt][1], acc[mt][nt][2], acc[mt][nt][3],
                         af[mt][0], af[mt][1], af[mt][2], af[mt][3],
                         bfr[nt][0], bfr[nt][1]);
        }
        __syncthreads();
    }

    // --- epilogue ---
#pragma unroll
    for (int mt = 0; mt < 4; mt++) {
#pragma unroll
        for (int nt = 0; nt < WNT; nt++) {
            int r = m0 + wm * 64 + mt * 16 + lr;
            int c = n0 + wn * (8 * WNT) + nt * 8 + 2 * lc;
            if (MODE == 0) {
                float b0 = bias[c], b1 = bias[c + 1];
                *(float2*)&C[(size_t)r * N + c] =
                    make_float2(acc[mt][nt][0] + b0, acc[mt][nt][1] + b1);
                *(float2*)&C[(size_t)(r + 8) * N + c] =
                    make_float2(acc[mt][nt][2] + b0, acc[mt][nt][3] + b1);
            } else {
                qkv_store2(r, c, acc[mt][nt][0], acc[mt][nt][1]);
                qkv_store2(r + 8, c, acc[mt][nt][2], acc[mt][nt][3]);
            }
        }
    }
}

#define G1_SMEM (GSTAGES * (128 * GAS + 32 * (256 + 8)) * 4)
#define G2_SMEM (GSTAGES * (128 * GAS + 32 * (128 + 8)) * 4)

// ---------------------------------------------------------------------------
// Flash attention v3: CTA = (b*h, 128-row Q tile), 256 threads, warp owns
// 16 rows. P stays in REGISTERS: accumulator regs are fed directly as
// A-fragments of the O-phase mma; the layout mismatch (acc cols {2q,2q+1}
// vs A-frag cols {q,q+4}) is fixed by loading V with a within-8-row
// permutation sigma(r) = (r>>1) + 4*(r&1). K unpermuted; softmax row ops are
// permutation-invariant, so numerics are identical to the smem version.
// ---------------------------------------------------------------------------
#define SKS 68
#define SVS 72
#define ATTN_SMEM_BYTES ((2 * 128 * SKS + 2 * 128 * SVS) * 4)

__global__ __launch_bounds__(256, 1)
void attn_kernel() {
    extern __shared__ float sm[];
    float* sKb = sm;                    // [2][128*SKS]
    float* sVb = sm + 2 * 128 * SKS;    // [2][128*SVS]
    float* qstage = sVb + 128 * SVS;    // Q staged in V buffer 1 (consumed first)

    const int t = threadIdx.x;
    const int lane = t & 31;
    const int warp = t >> 5;       // 0..7
    const int lr = lane >> 2;      // 0..7
    const int lc = lane & 3;       // 0..3
    const int rb = warp * 16;
    const int bh = blockIdx.y;
    const int q0 = blockIdx.x * 128;
    const size_t base = (size_t)bh * SEQ * HD;

    auto kvload = [&](int s, int kt) {
        float* dk = sKb + s * 128 * SKS;
        float* dv = sVb + s * 128 * SVS;
        const size_t gb = base + (size_t)kt * 128 * HD;
#pragma unroll
        for (int j = 0; j < 8; j++) {
            int i = t + j * 256;
            int r = i >> 4, c4 = (i & 15) << 2;
            cpa16(dk + r * SKS + c4, g_k + gb + r * HD + c4);
            // V row permutation: smem row (r&~7) | ((r&7)>>1) + 4*(r&1)
            int rv = (r & ~7) | (((r & 7) >> 1) + ((r & 1) << 2));
            cpa16(dv + rv * SVS + c4, g_v + gb + r * HD + c4);
        }
    };

    // stage Q -> regs
#pragma unroll
    for (int j = 0; j < 8; j++) {
        int i = t + j * 256;
        int r = i >> 4, c4 = (i & 15) << 2;
        cpa16(qstage + r * SKS + c4, g_q + base + (size_t)(q0 + r) * HD + c4);
    }
    cpa_commit();
    kvload(0, 0);
    cpa_commit();
    cpa_wait<1>();          // Q done (KV0 may be pending)
    __syncthreads();

    uint32_t qf[8][4];
#pragma unroll
    for (int ks = 0; ks < 8; ks++) {
        qf[ks][0] = fb(qstage[(rb + lr) * SKS + ks * 8 + lc]);
        qf[ks][1] = fb(qstage[(rb + lr + 8) * SKS + ks * 8 + lc]);
        qf[ks][2] = fb(qstage[(rb + lr) * SKS + ks * 8 + lc + 4]);
        qf[ks][3] = fb(qstage[(rb + lr + 8) * SKS + ks * 8 + lc + 4]);
    }
    __syncthreads();        // Q consumed; V buffer 1 free for kvload(1)

    float m0 = -1e30f, m1 = -1e30f, l0 = 0.f, l1 = 0.f;
    float accO[8][4];
#pragma unroll
    for (int nt = 0; nt < 8; nt++)
#pragma unroll
        for (int e = 0; e < 4; e++) accO[nt][e] = 0.f;

    for (int kt = 0; kt < SEQ / 128; kt++) {
        const int s = kt & 1;
        if (kt + 1 < SEQ / 128) {
            kvload(s ^ 1, kt + 1);
            cpa_commit();
            cpa_wait<1>();
        } else {
            cpa_wait<0>();
        }
        __syncthreads();

        const float* sKs = sKb + s * 128 * SKS;
        const float* sVs = sVb + s * 128 * SVS;

        // ---- S = Q * K^T, warp tile 16 x 128 ----
        float accS[16][4];
#pragma unroll
        for (int nt = 0; nt < 16; nt++)
#pragma unroll
            for (int e = 0; e < 4; e++) accS[nt][e] = 0.f;

#pragma unroll
        for (int nt = 0; nt < 16; nt++) {
#pragma unroll
            for (int ks = 0; ks < 8; ks++) {
                uint32_t b0 = fb(sKs[(nt * 8 + lr) * SKS + ks * 8 + lc]);
                uint32_t b1 = fb(sKs[(nt * 8 + lr) * SKS + ks * 8 + lc + 4]);
                mma8(accS[nt][0], accS[nt][1], accS[nt][2], accS[nt][3],
                     qf[ks][0], qf[ks][1], qf[ks][2], qf[ks][3], b0, b1);
            }
        }

        // ---- warp-local online softmax, P stays in accS ----
        float mx0 = -1e30f, mx1 = -1e30f;
#pragma unroll
        for (int nt = 0; nt < 16; nt++) {
            mx0 = fmaxf(mx0, fmaxf(accS[nt][0], accS[nt][1]));
            mx1 = fmaxf(mx1, fmaxf(accS[nt][2], accS[nt][3]));
        }
        mx0 = fmaxf(mx0, __shfl_xor_sync(0xffffffffu, mx0, 1));
        mx0 = fmaxf(mx0, __shfl_xor_sync(0xffffffffu, mx0, 2));
        mx1 = fmaxf(mx1, __shfl_xor_sync(0xffffffffu, mx1, 1));
        mx1 = fmaxf(mx1, __shfl_xor_sync(0xffffffffu, mx1, 2));

        float nm0 = fmaxf(m0, mx0), nm1 = fmaxf(m1, mx1);
        float cr0 = __expf(m0 - nm0), cr1 = __expf(m1 - nm1);
        float s0 = 0.f, s1 = 0.f;
#pragma unroll
        for (int nt = 0; nt < 16; nt++) {
            accS[nt][0] = __expf(accS[nt][0] - nm0);
            accS[nt][1] = __expf(accS[nt][1] - nm0);
            accS[nt][2] = __expf(accS[nt][2] - nm1);
            accS[nt][3] = __expf(accS[nt][3] - nm1);
            s0 += accS[nt][0] + accS[nt][1];
            s1 += accS[nt][2] + accS[nt][3];
        }
        s0 += __shfl_xor_sync(0xffffffffu, s0, 1);
        s0 += __shfl_xor_sync(0xffffffffu, s0, 2);
        s1 += __shfl_xor_sync(0xffffffffu, s1, 1);
        s1 += __shfl_xor_sync(0xffffffffu, s1, 2);
        l0 = l0 * cr0 + s0;
        l1 = l1 * cr1 + s1;
        m0 = nm0;
        m1 = nm1;

#pragma unroll
        for (int nt = 0; nt < 8; nt++) {
            accO[nt][0] *= cr0;
            accO[nt][1] *= cr0;
            accO[nt][2] *= cr1;
            accO[nt][3] *= cr1;
        }

        // ---- O += P * V : P fed straight from accS registers ----
        // a0<-c0, a1<-c2, a2<-c1, a3<-c3 ; V rows sigma-permuted at load.
#pragma unroll
        for (int g = 0; g < 16; g++) {
            uint32_t a0 = fbt(accS[g][0]);
            uint32_t a1 = fbt(accS[g][2]);
            uint32_t a2 = fbt(accS[g][1]);
            uint32_t a3 = fbt(accS[g][3]);
#pragma unroll
            for (int nt = 0; nt < 8; nt++) {
                uint32_t b0 = fb(sVs[(g * 8 + lc) * SVS + nt * 8 + lr]);
                uint32_t b1 = fb(sVs[(g * 8 + lc + 4) * SVS + nt * 8 + lr]);
                mma8(accO[nt][0], accO[nt][1], accO[nt][2], accO[nt][3],
                     a0, a1, a2, a3, b0, b1);
            }
        }
        __syncthreads();   // all warps done with buffer s before overwrite
    }

    // ---- normalize & store [b, n, h*64+d] ----
    const int b = bh >> 4;
    const int h = bh & 15;
    const float i0 = 1.f / l0, i1 = 1.f / l1;
    const int r0g = q0 + rb + lr;
    const int r1g = r0g + 8;
#pragma unroll
    for (int nt = 0; nt < 8; nt++) {
        int d = nt * 8 + 2 * lc;
        *(float2*)&g_att[((size_t)(b * SEQ + r0g)) * EMB + h * HD + d] =
            make_float2(accO[nt][0] * i0, accO[nt][1] * i0);
        *(float2*)&g_att[((size_t)(b * SEQ + r1g)) * EMB + h * HD + d] =
            make_float2(accO[nt][2] * i1, accO[nt][3] * i1);
    }
}

// ---------------------------------------------------------------------------
// Launch
// ---------------------------------------------------------------------------
extern "C" void kernel_launch(void* const* d_in, const int* in_sizes, int n_in,
                              void* d_out, int out_size) {
    const float* x    = (const float*)d_in[0];
    const float* Wqkv = (const float*)d_in[1];
    const float* Wout = (const float*)d_in[2];
    const float* bout = (const float*)d_in[3];
    float* out = (float*)d_out;

    static bool attr_done = false;
    if (!attr_done) {
        cudaFuncSetAttribute((const void*)gemm_tf32<1, 8>,
                             cudaFuncAttributeMaxDynamicSharedMemorySize, G1_SMEM);
        cudaFuncSetAttribute((const void*)gemm_tf32<0, 4>,
                             cudaFuncAttributeMaxDynamicSharedMemorySize, G2_SMEM);
        cudaFuncSetAttribute((const void*)attn_kernel,
                             cudaFuncAttributeMaxDynamicSharedMemorySize, ATTN_SMEM_BYTES);
        attr_done = true;
    }

    // 1) QKV projection (128x256 tiles) with head-split tf32 scatter epilogue
    gemm_tf32<1, 8><<<dim3(NQKV / 256, MTOT / 128), 256, G1_SMEM>>>(
        x, Wqkv, nullptr, nullptr, NQKV);

    // 2) flash attention (register-P)
    attn_kernel<<<dim3(SEQ / 128, BB * NH), 256, ATTN_SMEM_BYTES>>>();

    // 3) output projection + bias (128x128 tiles)
    void* attp = nullptr;
    cudaGetSymbolAddress(&attp, g_att);
    gemm_tf32<0, 4><<<dim3(EMB / 128, MTOT / 128), 256, G2_SMEM>>>(
        (const float*)attp, Wout, bout, out, EMB);
}

// round 9
// speedup vs baseline: 2.2872x; 1.0109x over previous
#include <cuda_runtime.h>
#include <cstdint>

// ---------------------------------------------------------------------------
// Problem constants
// ---------------------------------------------------------------------------
#define BB    4
#define SEQ   2048
#define EMB   1024
#define NH    16
#define HD    64
#define MTOT  (BB * SEQ)          // 8192 rows
#define NQKV  (3 * EMB)           // 3072
#define KDIM  1024

// ---------------------------------------------------------------------------
// Scratch (device globals: allocation-free)
// ---------------------------------------------------------------------------
__device__ float g_x32[(size_t)MTOT * EMB];         // tf32-rounded x
__device__ float g_wqkv[(size_t)EMB * NQKV];        // tf32-rounded Wqkv (row-major)
__device__ float g_wout[(size_t)EMB * EMB];         // tf32-rounded Wout
__device__ float g_q[(size_t)BB * NH * SEQ * HD];   // [b,h,n,d] tf32, Q pre-scaled
__device__ float g_k[(size_t)BB * NH * SEQ * HD];   // tf32
__device__ float g_v[(size_t)BB * NH * SEQ * HD];   // tf32
__device__ float g_att[(size_t)MTOT * EMB];         // [b,n,h*d] tf32-rounded

// ---------------------------------------------------------------------------
// Helpers
// ---------------------------------------------------------------------------
__device__ __forceinline__ float to_tf32(float x) {
    uint32_t u;
    asm("cvt.rna.tf32.f32 %0, %1;" : "=r"(u) : "f"(x));
    return __uint_as_float(u);
}
__device__ __forceinline__ uint32_t fb(float x) { return __float_as_uint(x); }
__device__ __forceinline__ uint32_t fbt(float x) { return fb(to_tf32(x)); }

__device__ __forceinline__ void mma8(float& c0, float& c1, float& c2, float& c3,
                                     uint32_t a0, uint32_t a1, uint32_t a2, uint32_t a3,
                                     uint32_t b0, uint32_t b1) {
    asm volatile(
        "mma.sync.aligned.m16n8k8.row.col.f32.tf32.tf32.f32 "
        "{%0,%1,%2,%3}, {%4,%5,%6,%7}, {%8,%9}, {%0,%1,%2,%3};"
        : "+f"(c0), "+f"(c1), "+f"(c2), "+f"(c3)
        : "r"(a0), "r"(a1), "r"(a2), "r"(a3), "r"(b0), "r"(b1));
}

__device__ __forceinline__ void cpa16(void* dst, const void* src) {
    uint32_t d = (uint32_t)__cvta_generic_to_shared(dst);
    asm volatile("cp.async.cg.shared.global [%0], [%1], 16;" :: "r"(d), "l"(src));
}
__device__ __forceinline__ void cpa_commit() {
    asm volatile("cp.async.commit_group;");
}
template <int N>
__device__ __forceinline__ void cpa_wait() {
    asm volatile("cp.async.wait_group %0;" :: "n"(N));
}

// QKV scatter (vectorized): store tf32; fold softmax scale (2^-3) into Q
__device__ __forceinline__ void qkv_store2(int m, int c, float v0, float v1) {
    int which = c >> 10;
    int r = c & 1023;
    int h = r >> 6;
    int d = r & 63;
    int b = m >> 11;
    int n = m & 2047;
    size_t off = (((size_t)(b * NH + h)) * SEQ + n) * HD + d;
    if (which == 0)
        *(float2*)&g_q[off] = make_float2(to_tf32(v0 * 0.125f), to_tf32(v1 * 0.125f));
    else if (which == 1)
        *(float2*)&g_k[off] = make_float2(to_tf32(v0), to_tf32(v1));
    else
        *(float2*)&g_v[off] = make_float2(to_tf32(v0), to_tf32(v1));
}

// ---------------------------------------------------------------------------
// Pre-round: tf32 RNA rounding of inputs (grid-stride, float4)
// ---------------------------------------------------------------------------
__global__ __launch_bounds__(256)
void round_kernel(const float4* __restrict__ src, float4* __restrict__ dst, int n4) {
    for (int i = blockIdx.x * blockDim.x + threadIdx.x; i < n4;
         i += gridDim.x * blockDim.x) {
        float4 v = src[i];
        v.x = to_tf32(v.x); v.y = to_tf32(v.y);
        v.z = to_tf32(v.z); v.w = to_tf32(v.w);
        dst[i] = v;
    }
}

// ---------------------------------------------------------------------------
// tf32 GEMM, 3-stage cp.async pipeline. C[M x N] = A[M x 1024] * B[1024 x N].
// A and B PRE-ROUNDED to tf32 in gmem -> no cvt in hot loop.
// CTA tile 128 x (32*WNT), 256 threads, warps 2(m) x 4(n), warp tile 64 x 8*WNT.
// MODE 0: C = acc + bias ; MODE 1: scatter into g_q/g_k/g_v
// ---------------------------------------------------------------------------
#define GAS 36
#define GSTAGES 3

template <int MODE, int WNT, int MINB>
__global__ __launch_bounds__(256, MINB)
void gemm_tf32(const float* __restrict__ A, const float* __restrict__ Bm,
               const float* __restrict__ bias, float* __restrict__ C, int N) {
    constexpr int TN  = 32 * WNT;      // CTA N tile
    constexpr int GBS = TN + 8;        // Bs row stride (≡8 mod 32: conflict-free)
    constexpr int QPR = TN / 4;        // float4 per B row

    extern __shared__ float smg[];
    float* As = smg;                          // [GSTAGES][128*GAS]
    float* Bs = smg + GSTAGES * 128 * GAS;    // [GSTAGES][32*GBS]

    const int t = threadIdx.x;
    const int lane = t & 31;
    const int warp = t >> 5;
    const int wm = warp >> 2;       // 0..1
    const int wn = warp & 3;        // 0..3
    const int lr = lane >> 2;       // 0..7
    const int lc = lane & 3;        // 0..3
    const int m0 = blockIdx.y * 128;
    const int n0 = blockIdx.x * TN;

    float acc[4][WNT][4];
#pragma unroll
    for (int mt = 0; mt < 4; mt++)
#pragma unroll
        for (int nt = 0; nt < WNT; nt++)
#pragma unroll
            for (int e = 0; e < 4; e++) acc[mt][nt][e] = 0.f;

    auto fill = [&](int s, int kc) {
        float* as = As + s * 128 * GAS;
        float* bs = Bs + s * 32 * GBS;
#pragma unroll
        for (int j = 0; j < 4; j++) {          // A: 128 x 32 floats
            int idx = t + j * 256;
            int ra = idx >> 3, ca = (idx & 7) << 2;
            cpa16(as + ra * GAS + ca, A + (size_t)(m0 + ra) * KDIM + kc + ca);
        }
#pragma unroll
        for (int j = 0; j < WNT; j++) {        // B: 32 x TN floats
            int idx = t + j * 256;
            int rb = idx / QPR, cb = (idx % QPR) << 2;
            cpa16(bs + rb * GBS + cb, Bm + (size_t)(kc + rb) * N + n0 + cb);
        }
    };

    const int NC = KDIM / 32;    // 32 chunks
    fill(0, 0);  cpa_commit();
    fill(1, 32); cpa_commit();

    for (int c = 0; c < NC; c++) {
        if (c + 2 < NC) {
            fill((c + 2) % GSTAGES, (c + 2) * 32);
            cpa_commit();
            cpa_wait<2>();
        } else if (c + 1 < NC) {
            cpa_wait<1>();
        } else {
            cpa_wait<0>();
        }
        __syncthreads();

        const float* as = As + (c % GSTAGES) * 128 * GAS;
        const float* bs = Bs + (c % GSTAGES) * 32 * GBS;
#pragma unroll
        for (int ks = 0; ks < 4; ks++) {
            uint32_t af[4][4];
#pragma unroll
            for (int mt = 0; mt < 4; mt++) {
                int rbse = wm * 64 + mt * 16;
                af[mt][0] = fb(as[(rbse + lr) * GAS + ks * 8 + lc]);
                af[mt][1] = fb(as[(rbse + lr + 8) * GAS + ks * 8 + lc]);
                af[mt][2] = fb(as[(rbse + lr) * GAS + ks * 8 + lc + 4]);
                af[mt][3] = fb(as[(rbse + lr + 8) * GAS + ks * 8 + lc + 4]);
            }
            uint32_t bfr[WNT][2];
#pragma unroll
            for (int nt = 0; nt < WNT; nt++) {
                int cb = wn * (8 * WNT) + nt * 8 + lr;
                bfr[nt][0] = fb(bs[(ks * 8 + lc) * GBS + cb]);
                bfr[nt][1] = fb(bs[(ks * 8 + lc + 4) * GBS + cb]);
            }
#pragma unroll
            for (int mt = 0; mt < 4; mt++)
#pragma unroll
                for (int nt = 0; nt < WNT; nt++)
                    mma8(acc[mt][nt][0], acc[mt][nt][1], acc[mt][nt][2], acc[mt][nt][3],
                         af[mt][0], af[mt][1], af[mt][2], af[mt][3],
                         bfr[nt][0], bfr[nt][1]);
        }
        __syncthreads();
    }

    // --- epilogue ---
#pragma unroll
    for (int mt = 0; mt < 4; mt++) {
#pragma unroll
        for (int nt = 0; nt < WNT; nt++) {
            int r = m0 + wm * 64 + mt * 16 + lr;
            int c = n0 + wn * (8 * WNT) + nt * 8 + 2 * lc;
            if (MODE == 0) {
                float b0 = bias[c], b1 = bias[c + 1];
                *(float2*)&C[(size_t)r * N + c] =
                    make_float2(acc[mt][nt][0] + b0, acc[mt][nt][1] + b1);
                *(float2*)&C[(size_t)(r + 8) * N + c] =
                    make_float2(acc[mt][nt][2] + b0, acc[mt][nt][3] + b1);
            } else {
                qkv_store2(r, c, acc[mt][nt][0], acc[mt][nt][1]);
                qkv_store2(r + 8, c, acc[mt][nt][2], acc[mt][nt][3]);
            }
        }
    }
}

#define G1_SMEM (GSTAGES * (128 * GAS + 32 * (256 + 8)) * 4)
#define G2_SMEM (GSTAGES * (128 * GAS + 32 * (128 + 8)) * 4)

// ---------------------------------------------------------------------------
// Flash attention v3 (register-P, permuted V). Unchanged from R8 except the
// output store rounds to tf32 so GEMM2's A is pre-rounded.
// ---------------------------------------------------------------------------
#define SKS 68
#define SVS 72
#define ATTN_SMEM_BYTES ((2 * 128 * SKS + 2 * 128 * SVS) * 4)

__global__ __launch_bounds__(256, 1)
void attn_kernel() {
    extern __shared__ float sm[];
    float* sKb = sm;                    // [2][128*SKS]
    float* sVb = sm + 2 * 128 * SKS;    // [2][128*SVS]
    float* qstage = sVb + 128 * SVS;    // Q staged in V buffer 1

    const int t = threadIdx.x;
    const int lane = t & 31;
    const int warp = t >> 5;       // 0..7
    const int lr = lane >> 2;      // 0..7
    const int lc = lane & 3;       // 0..3
    const int rb = warp * 16;
    const int bh = blockIdx.y;
    const int q0 = blockIdx.x * 128;
    const size_t base = (size_t)bh * SEQ * HD;

    auto kvload = [&](int s, int kt) {
        float* dk = sKb + s * 128 * SKS;
        float* dv = sVb + s * 128 * SVS;
        const size_t gb = base + (size_t)kt * 128 * HD;
#pragma unroll
        for (int j = 0; j < 8; j++) {
            int i = t + j * 256;
            int r = i >> 4, c4 = (i & 15) << 2;
            cpa16(dk + r * SKS + c4, g_k + gb + r * HD + c4);
            int rv = (r & ~7) | (((r & 7) >> 1) + ((r & 1) << 2));
            cpa16(dv + rv * SVS + c4, g_v + gb + r * HD + c4);
        }
    };

#pragma unroll
    for (int j = 0; j < 8; j++) {
        int i = t + j * 256;
        int r = i >> 4, c4 = (i & 15) << 2;
        cpa16(qstage + r * SKS + c4, g_q + base + (size_t)(q0 + r) * HD + c4);
    }
    cpa_commit();
    kvload(0, 0);
    cpa_commit();
    cpa_wait<1>();
    __syncthreads();

    uint32_t qf[8][4];
#pragma unroll
    for (int ks = 0; ks < 8; ks++) {
        qf[ks][0] = fb(qstage[(rb + lr) * SKS + ks * 8 + lc]);
        qf[ks][1] = fb(qstage[(rb + lr + 8) * SKS + ks * 8 + lc]);
        qf[ks][2] = fb(qstage[(rb + lr) * SKS + ks * 8 + lc + 4]);
        qf[ks][3] = fb(qstage[(rb + lr + 8) * SKS + ks * 8 + lc + 4]);
    }
    __syncthreads();

    float m0 = -1e30f, m1 = -1e30f, l0 = 0.f, l1 = 0.f;
    float accO[8][4];
#pragma unroll
    for (int nt = 0; nt < 8; nt++)
#pragma unroll
        for (int e = 0; e < 4; e++) accO[nt][e] = 0.f;

    for (int kt = 0; kt < SEQ / 128; kt++) {
        const int s = kt & 1;
        if (kt + 1 < SEQ / 128) {
            kvload(s ^ 1, kt + 1);
            cpa_commit();
            cpa_wait<1>();
        } else {
            cpa_wait<0>();
        }
        __syncthreads();

        const float* sKs = sKb + s * 128 * SKS;
        const float* sVs = sVb + s * 128 * SVS;

        float accS[16][4];
#pragma unroll
        for (int nt = 0; nt < 16; nt++)
#pragma unroll
            for (int e = 0; e < 4; e++) accS[nt][e] = 0.f;

#pragma unroll
        for (int nt = 0; nt < 16; nt++) {
#pragma unroll
            for (int ks = 0; ks < 8; ks++) {
                uint32_t b0 = fb(sKs[(nt * 8 + lr) * SKS + ks * 8 + lc]);
                uint32_t b1 = fb(sKs[(nt * 8 + lr) * SKS + ks * 8 + lc + 4]);
                mma8(accS[nt][0], accS[nt][1], accS[nt][2], accS[nt][3],
                     qf[ks][0], qf[ks][1], qf[ks][2], qf[ks][3], b0, b1);
            }
        }

        float mx0 = -1e30f, mx1 = -1e30f;
#pragma unroll
        for (int nt = 0; nt < 16; nt++) {
            mx0 = fmaxf(mx0, fmaxf(accS[nt][0], accS[nt][1]));
            mx1 = fmaxf(mx1, fmaxf(accS[nt][2], accS[nt][3]));
        }
        mx0 = fmaxf(mx0, __shfl_xor_sync(0xffffffffu, mx0, 1));
        mx0 = fmaxf(mx0, __shfl_xor_sync(0xffffffffu, mx0, 2));
        mx1 = fmaxf(mx1, __shfl_xor_sync(0xffffffffu, mx1, 1));
        mx1 = fmaxf(mx1, __shfl_xor_sync(0xffffffffu, mx1, 2));

        float nm0 = fmaxf(m0, mx0), nm1 = fmaxf(m1, mx1);
        float cr0 = __expf(m0 - nm0), cr1 = __expf(m1 - nm1);
        float s0 = 0.f, s1 = 0.f;
#pragma unroll
        for (int nt = 0; nt < 16; nt++) {
            accS[nt][0] = __expf(accS[nt][0] - nm0);
            accS[nt][1] = __expf(accS[nt][1] - nm0);
            accS[nt][2] = __expf(accS[nt][2] - nm1);
            accS[nt][3] = __expf(accS[nt][3] - nm1);
            s0 += accS[nt][0] + accS[nt][1];
            s1 += accS[nt][2] + accS[nt][3];
        }
        s0 += __shfl_xor_sync(0xffffffffu, s0, 1);
        s0 += __shfl_xor_sync(0xffffffffu, s0, 2);
        s1 += __shfl_xor_sync(0xffffffffu, s1, 1);
        s1 += __shfl_xor_sync(0xffffffffu, s1, 2);
        l0 = l0 * cr0 + s0;
        l1 = l1 * cr1 + s1;
        m0 = nm0;
        m1 = nm1;

#pragma unroll
        for (int nt = 0; nt < 8; nt++) {
            accO[nt][0] *= cr0;
            accO[nt][1] *= cr0;
            accO[nt][2] *= cr1;
            accO[nt][3] *= cr1;
        }

        // O += P * V : P fed straight from accS registers (sigma-permuted V)
#pragma unroll
        for (int g = 0; g < 16; g++) {
            uint32_t a0 = fbt(accS[g][0]);
            uint32_t a1 = fbt(accS[g][2]);
            uint32_t a2 = fbt(accS[g][1]);
            uint32_t a3 = fbt(accS[g][3]);
#pragma unroll
            for (int nt = 0; nt < 8; nt++) {
                uint32_t b0 = fb(sVs[(g * 8 + lc) * SVS + nt * 8 + lr]);
                uint32_t b1 = fb(sVs[(g * 8 + lc + 4) * SVS + nt * 8 + lr]);
                mma8(accO[nt][0], accO[nt][1], accO[nt][2], accO[nt][3],
                     a0, a1, a2, a3, b0, b1);
            }
        }
        __syncthreads();
    }

    // normalize & store [b, n, h*64+d], tf32-rounded for GEMM2
    const int b = bh >> 4;
    const int h = bh & 15;
    const float i0 = 1.f / l0, i1 = 1.f / l1;
    const int r0g = q0 + rb + lr;
    const int r1g = r0g + 8;
#pragma unroll
    for (int nt = 0; nt < 8; nt++) {
        int d = nt * 8 + 2 * lc;
        *(float2*)&g_att[((size_t)(b * SEQ + r0g)) * EMB + h * HD + d] =
            make_float2(to_tf32(accO[nt][0] * i0), to_tf32(accO[nt][1] * i0));
        *(float2*)&g_att[((size_t)(b * SEQ + r1g)) * EMB + h * HD + d] =
            make_float2(to_tf32(accO[nt][2] * i1), to_tf32(accO[nt][3] * i1));
    }
}

// ---------------------------------------------------------------------------
// Launch
// ---------------------------------------------------------------------------
extern "C" void kernel_launch(void* const* d_in, const int* in_sizes, int n_in,
                              void* d_out, int out_size) {
    const float* x    = (const float*)d_in[0];
    const float* Wqkv = (const float*)d_in[1];
    const float* Wout = (const float*)d_in[2];
    const float* bout = (const float*)d_in[3];
    float* out = (float*)d_out;

    static bool attr_done = false;
    if (!attr_done) {
        cudaFuncSetAttribute((const void*)gemm_tf32<1, 8, 1>,
                             cudaFuncAttributeMaxDynamicSharedMemorySize, G1_SMEM);
        cudaFuncSetAttribute((const void*)gemm_tf32<0, 4, 2>,
                             cudaFuncAttributeMaxDynamicSharedMemorySize, G2_SMEM);
        cudaFuncSetAttribute((const void*)attn_kernel,
                             cudaFuncAttributeMaxDynamicSharedMemorySize, ATTN_SMEM_BYTES);
        attr_done = true;
    }

    void* px = nullptr;  cudaGetSymbolAddress(&px, g_x32);
    void* pwq = nullptr; cudaGetSymbolAddress(&pwq, g_wqkv);
    void* pwo = nullptr; cudaGetSymbolAddress(&pwo, g_wout);
    void* patt = nullptr; cudaGetSymbolAddress(&patt, g_att);

    // 0) pre-round inputs to tf32 (hot loops then need no cvt)
    round_kernel<<<1184, 256>>>((const float4*)x, (float4*)px, MTOT * EMB / 4);
    round_kernel<<<1184, 256>>>((const float4*)Wqkv, (float4*)pwq, EMB * NQKV / 4);
    round_kernel<<<592, 256>>>((const float4*)Wout, (float4*)pwo, EMB * EMB / 4);

    // 1) QKV projection (128x256 tiles) with head-split tf32 scatter epilogue
    gemm_tf32<1, 8, 1><<<dim3(NQKV / 256, MTOT / 128), 256, G1_SMEM>>>(
        (const float*)px, (const float*)pwq, nullptr, nullptr, NQKV);

    // 2) flash attention (register-P)
    attn_kernel<<<dim3(SEQ / 128, BB * NH), 256, ATTN_SMEM_BYTES>>>();

    // 3) output projection + bias (128x128 tiles, 2 CTA/SM)
    gemm_tf32<0, 4, 2><<<dim3(EMB / 128, MTOT / 128), 256, G2_SMEM>>>(
        (const float*)patt, (const float*)pwo, bout, out, EMB);
}

// round 10
// speedup vs baseline: 2.5207x; 1.1021x over previous
#include <cuda_runtime.h>
#include <cstdint>

// ---------------------------------------------------------------------------
// Problem constants
// ---------------------------------------------------------------------------
#define BB    4
#define SEQ   2048
#define EMB   1024
#define NH    16
#define HD    64
#define MTOT  8192
#define NQKV  3072
#define KDIM  1024

// ---------------------------------------------------------------------------
// Scratch (device globals: allocation-free)
// Packed-A layout (per [mtile][kchunk], 4096 floats):
//   [mb 0..7][ks 0..3][lane 0..31] float4 =
//     (A[R+lr][C+lc], A[R+lr+8][C+lc], A[R+lr][C+lc+4], A[R+lr+8][C+lc+4])
//   R = mtile*128 + mb*16, C = kchunk*32 + ks*8, lr=lane>>2, lc=lane&3
// Packed-B layout (per [ntile][kchunk], 8192 floats):
//   [nb 0..31][ks 0..3][lane] float2 = (B[K+lc][N+lr], B[K+4+lc][N+lr])
//   N = ntile*256 + nb*8, K = kchunk*32 + ks*8
// ---------------------------------------------------------------------------
__device__ float g_xp[(size_t)(MTOT / 128) * (KDIM / 32) * 4096];
__device__ float g_wqkvp[(size_t)(NQKV / 256) * (KDIM / 32) * 8192];
__device__ float g_woutp[(size_t)(EMB / 256) * (KDIM / 32) * 8192];
__device__ float g_attp[(size_t)(MTOT / 128) * (EMB / 32) * 4096];
__device__ float g_q[(size_t)BB * NH * SEQ * HD];   // [b,h,n,d] tf32, Q pre-scaled
__device__ float g_k[(size_t)BB * NH * SEQ * HD];   // tf32
__device__ float g_v[(size_t)BB * NH * SEQ * HD];   // tf32

// ---------------------------------------------------------------------------
// Helpers
// ---------------------------------------------------------------------------
__device__ __forceinline__ float to_tf32(float x) {
    uint32_t u;
    asm("cvt.rna.tf32.f32 %0, %1;" : "=r"(u) : "f"(x));
    return __uint_as_float(u);
}
__device__ __forceinline__ uint32_t fb(float x) { return __float_as_uint(x); }
__device__ __forceinline__ uint32_t fbt(float x) { return fb(to_tf32(x)); }

__device__ __forceinline__ void mma8(float& c0, float& c1, float& c2, float& c3,
                                     uint32_t a0, uint32_t a1, uint32_t a2, uint32_t a3,
                                     uint32_t b0, uint32_t b1) {
    asm volatile(
        "mma.sync.aligned.m16n8k8.row.col.f32.tf32.tf32.f32 "
        "{%0,%1,%2,%3}, {%4,%5,%6,%7}, {%8,%9}, {%0,%1,%2,%3};"
        : "+f"(c0), "+f"(c1), "+f"(c2), "+f"(c3)
        : "r"(a0), "r"(a1), "r"(a2), "r"(a3), "r"(b0), "r"(b1));
}

__device__ __forceinline__ void cpa16(void* dst, const void* src) {
    uint32_t d = (uint32_t)__cvta_generic_to_shared(dst);
    asm volatile("cp.async.cg.shared.global [%0], [%1], 16;" :: "r"(d), "l"(src));
}
__device__ __forceinline__ void cpa_commit() {
    asm volatile("cp.async.commit_group;");
}
template <int N>
__device__ __forceinline__ void cpa_wait() {
    asm volatile("cp.async.wait_group %0;" :: "n"(N));
}

// QKV scatter (vectorized): store tf32; fold softmax scale (2^-3) into Q
__device__ __forceinline__ void qkv_store2(int m, int c, float v0, float v1) {
    int which = c >> 10;
    int r = c & 1023;
    int h = r >> 6;
    int d = r & 63;
    int b = m >> 11;
    int n = m & 2047;
    size_t off = (((size_t)(b * NH + h)) * SEQ + n) * HD + d;
    if (which == 0)
        *(float2*)&g_q[off] = make_float2(to_tf32(v0 * 0.125f), to_tf32(v1 * 0.125f));
    else if (which == 1)
        *(float2*)&g_k[off] = make_float2(to_tf32(v0), to_tf32(v1));
    else
        *(float2*)&g_v[off] = make_float2(to_tf32(v0), to_tf32(v1));
}

// ---------------------------------------------------------------------------
// Pack kernels (include tf32 RNA rounding)
// ---------------------------------------------------------------------------
// A: src row-major [rows][1024] -> packed. grid (kchunk=32, mtile=rows/128)
__global__ __launch_bounds__(256)
void pack_a(const float* __restrict__ src, float* __restrict__ dst) {
    __shared__ float ts[128][33];
    const int kc = blockIdx.x, mt = blockIdx.y;
    const int t = threadIdx.x;
#pragma unroll
    for (int j = 0; j < 4; j++) {
        int idx = t + j * 256;
        int r = idx >> 3, c4 = (idx & 7) * 4;
        float4 v = *(const float4*)(src + (size_t)(mt * 128 + r) * KDIM + kc * 32 + c4);
        ts[r][c4 + 0] = v.x; ts[r][c4 + 1] = v.y;
        ts[r][c4 + 2] = v.z; ts[r][c4 + 3] = v.w;
    }
    __syncthreads();
    float* out = dst + ((size_t)mt * 32 + kc) * 4096;
#pragma unroll
    for (int j = 0; j < 4; j++) {
        int o = t + j * 256;                       // float4 index 0..1023
        int mb = o >> 7, ks = (o >> 5) & 3, lane = o & 31;
        int lr = lane >> 2, lc = lane & 3;
        float4 v;
        v.x = to_tf32(ts[mb * 16 + lr][ks * 8 + lc]);
        v.y = to_tf32(ts[mb * 16 + lr + 8][ks * 8 + lc]);
        v.z = to_tf32(ts[mb * 16 + lr][ks * 8 + lc + 4]);
        v.w = to_tf32(ts[mb * 16 + lr + 8][ks * 8 + lc + 4]);
        *(float4*)(out + o * 4) = v;
    }
}

// B: src row-major [1024][N] -> packed. grid (kchunk=32, ntile=N/256)
__global__ __launch_bounds__(256)
void pack_b(const float* __restrict__ src, float* __restrict__ dst, int N) {
    __shared__ float ts[32][257];
    const int kc = blockIdx.x, ntile = blockIdx.y;
    const int t = threadIdx.x;
#pragma unroll
    for (int j = 0; j < 8; j++) {
        int idx = t + j * 256;
        int r = idx >> 6, c4 = (idx & 63) * 4;
        float4 v = *(const float4*)(src + (size_t)(kc * 32 + r) * N + ntile * 256 + c4);
        ts[r][c4 + 0] = v.x; ts[r][c4 + 1] = v.y;
        ts[r][c4 + 2] = v.z; ts[r][c4 + 3] = v.w;
    }
    __syncthreads();
    float* out = dst + ((size_t)ntile * 32 + kc) * 8192;
#pragma unroll
    for (int j = 0; j < 16; j++) {
        int o = t + j * 256;                       // float2 index 0..4095
        int nb = o >> 7, ks = (o >> 5) & 3, lane = o & 31;
        int lr = lane >> 2, lc = lane & 3;
        float2 v;
        v.x = to_tf32(ts[ks * 8 + lc][nb * 8 + lr]);
        v.y = to_tf32(ts[ks * 8 + 4 + lc][nb * 8 + lr]);
        *(float2*)(out + o * 2) = v;
    }
}

// ---------------------------------------------------------------------------
// Packed tf32 GEMM: C[M x N] = A[M x 1024] * B[1024 x N], fragment-packed
// operands. CTA tile 128x256, 256 thr, warps 2(m) x 4(n), warp tile 64x64.
// 4-stage cp.async pipeline, one __syncthreads per chunk.
// MODE 0: C = acc + bias ; MODE 1: scatter into g_q/g_k/g_v
// ---------------------------------------------------------------------------
#define PST 4
#define STAGE_FLOATS 12288            // A 4096 + B 8192
#define PG_SMEM (PST * STAGE_FLOATS * 4)

template <int MODE>
__global__ __launch_bounds__(256, 1)
void gemm_packed(const float* __restrict__ Ap, const float* __restrict__ Bp,
                 const float* __restrict__ bias, float* __restrict__ C, int N) {
    extern __shared__ float smp[];
    const int t = threadIdx.x;
    const int lane = t & 31;
    const int warp = t >> 5;
    const int wm = warp >> 2;       // 0..1
    const int wn = warp & 3;        // 0..3
    const int lr = lane >> 2;
    const int lc = lane & 3;
    const int mtile = blockIdx.y;
    const int ntile = blockIdx.x;

    float acc[4][8][4];
#pragma unroll
    for (int mt = 0; mt < 4; mt++)
#pragma unroll
        for (int nt = 0; nt < 8; nt++)
#pragma unroll
            for (int e = 0; e < 4; e++) acc[mt][nt][e] = 0.f;

    auto fill = [&](int s, int c) {
        float* as = smp + s * STAGE_FLOATS;
        float* bs = as + 4096;
        const float* ga = Ap + ((size_t)mtile * 32 + c) * 4096;
        const float* gb = Bp + ((size_t)ntile * 32 + c) * 8192;
#pragma unroll
        for (int j = 0; j < 4; j++) {
            int i4 = t + j * 256;
            cpa16(as + i4 * 4, ga + i4 * 4);
        }
#pragma unroll
        for (int j = 0; j < 8; j++) {
            int i4 = t + j * 256;
            cpa16(bs + i4 * 4, gb + i4 * 4);
        }
    };

#pragma unroll
    for (int c = 0; c < PST - 1; c++) { fill(c, c); cpa_commit(); }

    for (int c = 0; c < 32; c++) {
        cpa_wait<PST - 2>();
        __syncthreads();
        if (c + PST - 1 < 32) fill((c + PST - 1) % PST, c + PST - 1);
        cpa_commit();

        const float* as = smp + (c % PST) * STAGE_FLOATS;
        const float* bs = as + 4096;

        float4 a4[2][4];
        float2 b2[2][8];
        auto lfr = [&](int ks, int buf) {
#pragma unroll
            for (int mt = 0; mt < 4; mt++)
                a4[buf][mt] = *(const float4*)(as + (((wm * 4 + mt) * 4 + ks) * 32 + lane) * 4);
#pragma unroll
            for (int nt = 0; nt < 8; nt++)
                b2[buf][nt] = *(const float2*)(bs + (((wn * 8 + nt) * 4 + ks) * 32 + lane) * 2);
        };
        lfr(0, 0);
#pragma unroll
        for (int ks = 0; ks < 4; ks++) {
            if (ks < 3) lfr(ks + 1, (ks + 1) & 1);
            const int bsel = ks & 1;
#pragma unroll
            for (int mt = 0; mt < 4; mt++) {
                uint32_t A0 = fb(a4[bsel][mt].x), A1 = fb(a4[bsel][mt].y);
                uint32_t A2 = fb(a4[bsel][mt].z), A3 = fb(a4[bsel][mt].w);
#pragma unroll
                for (int nt = 0; nt < 8; nt++)
                    mma8(acc[mt][nt][0], acc[mt][nt][1], acc[mt][nt][2], acc[mt][nt][3],
                         A0, A1, A2, A3, fb(b2[bsel][nt].x), fb(b2[bsel][nt].y));
            }
        }
    }

    // --- epilogue ---
#pragma unroll
    for (int mt = 0; mt < 4; mt++) {
#pragma unroll
        for (int nt = 0; nt < 8; nt++) {
            int r = mtile * 128 + wm * 64 + mt * 16 + lr;
            int c = ntile * 256 + wn * 64 + nt * 8 + 2 * lc;
            if (MODE == 0) {
                float b0 = bias[c], b1 = bias[c + 1];
                *(float2*)&C[(size_t)r * N + c] =
                    make_float2(acc[mt][nt][0] + b0, acc[mt][nt][1] + b1);
                *(float2*)&C[(size_t)(r + 8) * N + c] =
                    make_float2(acc[mt][nt][2] + b0, acc[mt][nt][3] + b1);
            } else {
                qkv_store2(r, c, acc[mt][nt][0], acc[mt][nt][1]);
                qkv_store2(r + 8, c, acc[mt][nt][2], acc[mt][nt][3]);
            }
        }
    }
}

// ---------------------------------------------------------------------------
// Flash attention v3 (register-P, permuted V). Epilogue writes packed-A
// layout (g_attp) for GEMM2, tf32-rounded.
// ---------------------------------------------------------------------------
#define SKS 68
#define SVS 72
#define ATTN_SMEM_BYTES ((2 * 128 * SKS + 2 * 128 * SVS) * 4)

__global__ __launch_bounds__(256, 1)
void attn_kernel() {
    extern __shared__ float sm[];
    float* sKb = sm;                    // [2][128*SKS]
    float* sVb = sm + 2 * 128 * SKS;    // [2][128*SVS]
    float* qstage = sVb + 128 * SVS;    // Q staged in V buffer 1

    const int t = threadIdx.x;
    const int lane = t & 31;
    const int warp = t >> 5;       // 0..7
    const int lr = lane >> 2;      // 0..7
    const int lc = lane & 3;       // 0..3
    const int rb = warp * 16;
    const int bh = blockIdx.y;
    const int q0 = blockIdx.x * 128;
    const size_t base = (size_t)bh * SEQ * HD;

    auto kvload = [&](int s, int kt) {
        float* dk = sKb + s * 128 * SKS;
        float* dv = sVb + s * 128 * SVS;
        const size_t gb = base + (size_t)kt * 128 * HD;
#pragma unroll
        for (int j = 0; j < 8; j++) {
            int i = t + j * 256;
            int r = i >> 4, c4 = (i & 15) << 2;
            cpa16(dk + r * SKS + c4, g_k + gb + r * HD + c4);
            int rv = (r & ~7) | (((r & 7) >> 1) + ((r & 1) << 2));
            cpa16(dv + rv * SVS + c4, g_v + gb + r * HD + c4);
        }
    };

#pragma unroll
    for (int j = 0; j < 8; j++) {
        int i = t + j * 256;
        int r = i >> 4, c4 = (i & 15) << 2;
        cpa16(qstage + r * SKS + c4, g_q + base + (size_t)(q0 + r) * HD + c4);
    }
    cpa_commit();
    kvload(0, 0);
    cpa_commit();
    cpa_wait<1>();
    __syncthreads();

    uint32_t qf[8][4];
#pragma unroll
    for (int ks = 0; ks < 8; ks++) {
        qf[ks][0] = fb(qstage[(rb + lr) * SKS + ks * 8 + lc]);
        qf[ks][1] = fb(qstage[(rb + lr + 8) * SKS + ks * 8 + lc]);
        qf[ks][2] = fb(qstage[(rb + lr) * SKS + ks * 8 + lc + 4]);
        qf[ks][3] = fb(qstage[(rb + lr + 8) * SKS + ks * 8 + lc + 4]);
    }
    __syncthreads();

    float m0 = -1e30f, m1 = -1e30f, l0 = 0.f, l1 = 0.f;
    float accO[8][4];
#pragma unroll
    for (int nt = 0; nt < 8; nt++)
#pragma unroll
        for (int e = 0; e < 4; e++) accO[nt][e] = 0.f;

    for (int kt = 0; kt < SEQ / 128; kt++) {
        const int s = kt & 1;
        if (kt + 1 < SEQ / 128) {
            kvload(s ^ 1, kt + 1);
            cpa_commit();
            cpa_wait<1>();
        } else {
            cpa_wait<0>();
        }
        __syncthreads();

        const float* sKs = sKb + s * 128 * SKS;
        const float* sVs = sVb + s * 128 * SVS;

        float accS[16][4];
#pragma unroll
        for (int nt = 0; nt < 16; nt++)
#pragma unroll
            for (int e = 0; e < 4; e++) accS[nt][e] = 0.f;

#pragma unroll
        for (int nt = 0; nt < 16; nt++) {
#pragma unroll
            for (int ks = 0; ks < 8; ks++) {
                uint32_t b0 = fb(sKs[(nt * 8 + lr) * SKS + ks * 8 + lc]);
                uint32_t b1 = fb(sKs[(nt * 8 + lr) * SKS + ks * 8 + lc + 4]);
                mma8(accS[nt][0], accS[nt][1], accS[nt][2], accS[nt][3],
                     qf[ks][0], qf[ks][1], qf[ks][2], qf[ks][3], b0, b1);
            }
        }

        float mx0 = -1e30f, mx1 = -1e30f;
#pragma unroll
        for (int nt = 0; nt < 16; nt++) {
            mx0 = fmaxf(mx0, fmaxf(accS[nt][0], accS[nt][1]));
            mx1 = fmaxf(mx1, fmaxf(accS[nt][2], accS[nt][3]));
        }
        mx0 = fmaxf(mx0, __shfl_xor_sync(0xffffffffu, mx0, 1));
        mx0 = fmaxf(mx0, __shfl_xor_sync(0xffffffffu, mx0, 2));
        mx1 = fmaxf(mx1, __shfl_xor_sync(0xffffffffu, mx1, 1));
        mx1 = fmaxf(mx1, __shfl_xor_sync(0xffffffffu, mx1, 2));

        float nm0 = fmaxf(m0, mx0), nm1 = fmaxf(m1, mx1);
        float cr0 = __expf(m0 - nm0), cr1 = __expf(m1 - nm1);
        float s0 = 0.f, s1 = 0.f;
#pragma unroll
        for (int nt = 0; nt < 16; nt++) {
            accS[nt][0] = __expf(accS[nt][0] - nm0);
            accS[nt][1] = __expf(accS[nt][1] - nm0);
            accS[nt][2] = __expf(accS[nt][2] - nm1);
            accS[nt][3] = __expf(accS[nt][3] - nm1);
            s0 += accS[nt][0] + accS[nt][1];
            s1 += accS[nt][2] + accS[nt][3];
        }
        s0 += __shfl_xor_sync(0xffffffffu, s0, 1);
        s0 += __shfl_xor_sync(0xffffffffu, s0, 2);
        s1 += __shfl_xor_sync(0xffffffffu, s1, 1);
        s1 += __shfl_xor_sync(0xffffffffu, s1, 2);
        l0 = l0 * cr0 + s0;
        l1 = l1 * cr1 + s1;
        m0 = nm0;
        m1 = nm1;

#pragma unroll
        for (int nt = 0; nt < 8; nt++) {
            accO[nt][0] *= cr0;
            accO[nt][1] *= cr0;
            accO[nt][2] *= cr1;
            accO[nt][3] *= cr1;
        }

        // O += P * V : P fed straight from accS registers (sigma-permuted V)
#pragma unroll
        for (int g = 0; g < 16; g++) {
            uint32_t a0 = fbt(accS[g][0]);
            uint32_t a1 = fbt(accS[g][2]);
            uint32_t a2 = fbt(accS[g][1]);
            uint32_t a3 = fbt(accS[g][3]);
#pragma unroll
            for (int nt = 0; nt < 8; nt++) {
                uint32_t b0 = fb(sVs[(g * 8 + lc) * SVS + nt * 8 + lr]);
                uint32_t b1 = fb(sVs[(g * 8 + lc + 4) * SVS + nt * 8 + lr]);
                mma8(accO[nt][0], accO[nt][1], accO[nt][2], accO[nt][3],
                     a0, a1, a2, a3, b0, b1);
            }
        }
        __syncthreads();
    }

    // ---- normalize & store to g_attp in packed-A layout (tf32) ----
    const int b = bh >> 4;
    const int h = bh & 15;
    const float i0 = 1.f / l0, i1 = 1.f / l1;
    const int mtile = (b * SEQ + q0) >> 7;
    const int mb = warp;

    auto patt = [&](int cc, int rowhalf, float v) {
        int kchunk = cc >> 5, kk = cc & 31;
        int ksx = kk >> 3, pos = kk & 7;
        int lane2 = lr * 4 + (pos & 3);
        int slot = ((pos & 4) ? 2 : 0) + rowhalf;
        size_t idx = ((((size_t)mtile * 32 + kchunk) * 8 + mb) * 4 + ksx) * 128
                     + lane2 * 4 + slot;
        g_attp[idx] = to_tf32(v);
    };

#pragma unroll
    for (int nt = 0; nt < 8; nt++) {
        int c = h * 64 + nt * 8 + 2 * lc;
        patt(c, 0, accO[nt][0] * i0);
        patt(c + 1, 0, accO[nt][1] * i0);
        patt(c, 1, accO[nt][2] * i1);
        patt(c + 1, 1, accO[nt][3] * i1);
    }
}

// ---------------------------------------------------------------------------
// Launch
// ---------------------------------------------------------------------------
extern "C" void kernel_launch(void* const* d_in, const int* in_sizes, int n_in,
                              void* d_out, int out_size) {
    const float* x    = (const float*)d_in[0];
    const float* Wqkv = (const float*)d_in[1];
    const float* Wout = (const float*)d_in[2];
    const float* bout = (const float*)d_in[3];
    float* out = (float*)d_out;

    static bool attr_done = false;
    if (!attr_done) {
        cudaFuncSetAttribute((const void*)gemm_packed<1>,
                             cudaFuncAttributeMaxDynamicSharedMemorySize, PG_SMEM);
        cudaFuncSetAttribute((const void*)gemm_packed<0>,
                             cudaFuncAttributeMaxDynamicSharedMemorySize, PG_SMEM);
        cudaFuncSetAttribute((const void*)attn_kernel,
                             cudaFuncAttributeMaxDynamicSharedMemorySize, ATTN_SMEM_BYTES);
        attr_done = true;
    }

    void* pxp = nullptr;  cudaGetSymbolAddress(&pxp, g_xp);
    void* pwq = nullptr;  cudaGetSymbolAddress(&pwq, g_wqkvp);
    void* pwo = nullptr;  cudaGetSymbolAddress(&pwo, g_woutp);
    void* patt = nullptr; cudaGetSymbolAddress(&patt, g_attp);

    // 0) pack + round inputs into fragment-major layouts
    pack_a<<<dim3(KDIM / 32, MTOT / 128), 256>>>(x, (float*)pxp);
    pack_b<<<dim3(KDIM / 32, NQKV / 256), 256>>>(Wqkv, (float*)pwq, NQKV);
    pack_b<<<dim3(KDIM / 32, EMB / 256), 256>>>(Wout, (float*)pwo, EMB);

    // 1) QKV projection (packed 128x256 tiles) with head-split scatter epilogue
    gemm_packed<1><<<dim3(NQKV / 256, MTOT / 128), 256, PG_SMEM>>>(
        (const float*)pxp, (const float*)pwq, nullptr, nullptr, NQKV);

    // 2) flash attention (register-P), writes packed-A output for GEMM2
    attn_kernel<<<dim3(SEQ / 128, BB * NH), 256, ATTN_SMEM_BYTES>>>();

    // 3) output projection + bias (packed 128x256 tiles)
    gemm_packed<0><<<dim3(EMB / 256, MTOT / 128), 256, PG_SMEM>>>(
        (const float*)patt, (const float*)pwo, bout, out, EMB);
}